// round 6
// baseline (speedup 1.0000x reference)
#include <cuda_runtime.h>
#include <math.h>

#define B_  32
#define C_  256
#define H_  128
#define W_  128
#define HW  (H_ * W_)
#define HW4 (HW / 4)
#define NSPLIT 8

__device__ float g_avg [B_ * HW];
__device__ float g_max [B_ * HW];
__device__ float g_gate[B_ * HW];

// ---------------------------------------------------------------------------
// K1: channel-wise mean & max over y, smem-combined (writes only 8 MB).
// Pinned at ~80.7us across formulations — pattern ceiling; unchanged.
// ---------------------------------------------------------------------------
__global__ void __launch_bounds__(256) reduce_kernel(const float* __restrict__ y) {
    __shared__ float4 s_s[NSPLIT][32];
    __shared__ float4 s_m[NSPLIT][32];

    int lane = threadIdx.x & 31;
    int part = threadIdx.x >> 5;
    int q    = blockIdx.x * 32 + lane;
    int b    = q >> 12;
    int p4   = q & 4095;

    const float4* base = reinterpret_cast<const float4*>(y)
                       + ((size_t)b * C_ + (size_t)part * (C_ / NSPLIT)) * HW4 + p4;

    float4 s = make_float4(0.f, 0.f, 0.f, 0.f);
    float4 m = make_float4(-INFINITY, -INFINITY, -INFINITY, -INFINITY);

    #pragma unroll 8
    for (int c = 0; c < C_ / NSPLIT; c++) {
        float4 v = __ldcs(base + (size_t)c * HW4);
        s.x += v.x; s.y += v.y; s.z += v.z; s.w += v.w;
        m.x = fmaxf(m.x, v.x); m.y = fmaxf(m.y, v.y);
        m.z = fmaxf(m.z, v.z); m.w = fmaxf(m.w, v.w);
    }

    s_s[part][lane] = s;
    s_m[part][lane] = m;
    __syncthreads();

    if (part == 0) {
        #pragma unroll
        for (int p = 1; p < NSPLIT; p++) {
            float4 t  = s_s[p][lane];
            float4 tm = s_m[p][lane];
            s.x += t.x; s.y += t.y; s.z += t.z; s.w += t.w;
            m.x = fmaxf(m.x, tm.x); m.y = fmaxf(m.y, tm.y);
            m.z = fmaxf(m.z, tm.z); m.w = fmaxf(m.w, tm.w);
        }
        const float inv = 1.0f / (float)C_;
        s.x *= inv; s.y *= inv; s.z *= inv; s.w *= inv;
        reinterpret_cast<float4*>(g_avg)[q] = s;
        reinterpret_cast<float4*>(g_max)[q] = m;
    }
}

// ---------------------------------------------------------------------------
// K2: 3x3 conv + sigmoid -> gate. smem-tiled 32x32 with 34x34 halo.
// ---------------------------------------------------------------------------
__global__ void __launch_bounds__(256) gate_kernel(const float* __restrict__ conv_w) {
    __shared__ float s_avg[34][36];
    __shared__ float s_max[34][36];

    int blk = blockIdx.x;
    int b  = blk >> 4;
    int r  = blk & 15;
    int th = r >> 2;
    int tw = r & 3;
    int h0 = th * 32 - 1;
    int w0 = tw * 32 - 1;

    for (int i = threadIdx.x; i < 34 * 34; i += 256) {
        int lh = i / 34;
        int lw = i - lh * 34;
        int h  = h0 + lh;
        int w  = w0 + lw;
        float a = 0.f, m = 0.f;
        if (h >= 0 && h < H_ && w >= 0 && w < W_) {
            int si = b * HW + h * W_ + w;
            a = g_avg[si];
            m = g_max[si];
        }
        s_avg[lh][lw] = a;
        s_max[lh][lw] = m;
    }
    __syncthreads();

    float wa[9], wm[9];
    #pragma unroll
    for (int k = 0; k < 9; k++) { wa[k] = conv_w[k]; wm[k] = conv_w[9 + k]; }

    for (int i = threadIdx.x; i < 32 * 32; i += 256) {
        int lh = i >> 5;
        int lw = i & 31;
        float acc = 0.f;
        #pragma unroll
        for (int kh = 0; kh < 3; kh++)
            #pragma unroll
            for (int kw = 0; kw < 3; kw++) {
                acc = fmaf(s_avg[lh + kh][lw + kw], wa[kh * 3 + kw], acc);
                acc = fmaf(s_max[lh + kh][lw + kw], wm[kh * 3 + kw], acc);
            }
        int h = th * 32 + lh;
        int w = tw * 32 + lw;
        g_gate[b * HW + h * W_ + w] = 1.0f / (1.0f + expf(-acc));
    }
}

// ---------------------------------------------------------------------------
// K3: out = x * gate.  4 front-batched float4 pairs per thread (MLP_p1=8:
// 4 gate + 4 x loads issued before any store). Grid (4, 8192), block 256.
// Each block covers one contiguous 16 KB span of a plane.
// ---------------------------------------------------------------------------
__global__ void __launch_bounds__(256) mul_kernel(const float* __restrict__ x,
                                                  float* __restrict__ out) {
    int plane = blockIdx.y;                    // b*C + c
    int b     = plane >> 8;
    int p4    = blockIdx.x * 1024 + threadIdx.x;

    size_t base = (size_t)plane * HW4;
    const float4* xin = reinterpret_cast<const float4*>(x)   + base;
    float4*       dst = reinterpret_cast<float4*>(out)       + base;
    const float4* gp  = reinterpret_cast<const float4*>(g_gate) + (size_t)b * HW4;

    float4 g0 = __ldg(gp + p4);
    float4 g1 = __ldg(gp + p4 + 256);
    float4 g2 = __ldg(gp + p4 + 512);
    float4 g3 = __ldg(gp + p4 + 768);
    float4 x0 = __ldcs(xin + p4);
    float4 x1 = __ldcs(xin + p4 + 256);
    float4 x2 = __ldcs(xin + p4 + 512);
    float4 x3 = __ldcs(xin + p4 + 768);

    float4 o0, o1, o2, o3;
    o0.x = x0.x * g0.x; o0.y = x0.y * g0.y; o0.z = x0.z * g0.z; o0.w = x0.w * g0.w;
    o1.x = x1.x * g1.x; o1.y = x1.y * g1.y; o1.z = x1.z * g1.z; o1.w = x1.w * g1.w;
    o2.x = x2.x * g2.x; o2.y = x2.y * g2.y; o2.z = x2.z * g2.z; o2.w = x2.w * g2.w;
    o3.x = x3.x * g3.x; o3.y = x3.y * g3.y; o3.z = x3.z * g3.z; o3.w = x3.w * g3.w;

    __stcs(dst + p4,        o0);
    __stcs(dst + p4 + 256,  o1);
    __stcs(dst + p4 + 512,  o2);
    __stcs(dst + p4 + 768,  o3);
}

// ---------------------------------------------------------------------------
extern "C" void kernel_launch(void* const* d_in, const int* in_sizes, int n_in,
                              void* d_out, int out_size) {
    const float* x      = (const float*)d_in[0];
    const float* y      = (const float*)d_in[1];
    const float* conv_w = (const float*)d_in[2];
    float* out          = (float*)d_out;

    reduce_kernel<<<B_ * HW4 / 32, 256>>>(y);        // 4096 blocks
    gate_kernel<<<B_ * 16, 256>>>(conv_w);           // 512 blocks
    {
        dim3 grid(HW4 / 1024, B_ * C_);              // (4, 8192)
        mul_kernel<<<grid, 256>>>(x, out);
    }
}